// round 16
// baseline (speedup 1.0000x reference)
#include <cuda_runtime.h>
#include <cuda_bf16.h>
#include <cuda_fp16.h>
#include <cstdint>

#define BB 256     // batch
#define TT 256     // time steps
#define DD 64      // input dim
#define HH 512     // hidden
#define OO 10      // output classes

#define NBLK 128   // fused rec grid: 8 bt x 16 jt (all co-resident, 1/SM)
#define GRP  16    // CTAs per bt dependency group
#define HW   (HH / 2)   // packed fp16-pair row stride (uint32 units)

// ---------------- scratch (static device globals; no allocation allowed) ----
__device__ uint32_t g_xp0[TT * BB * HW];     // [t][b][h/2] fp16 pairs
__device__ uint32_t g_s0[2][BB * HW];        // seq0 ring, fp16 pairs
__device__ uint32_t g_h1[2][BB * HW];        // layer-1 h ring, fp16 pairs
__device__ float    g_hlast[BB * HH];

// split arrive/wait barriers, one pair per bt group; monotonic generations
__device__ unsigned g_cseq[8], g_gseq[8];    // seq0 barrier: count, gen
__device__ unsigned g_ch1[8],  g_gh1[8];     // h1 barrier: count, gen

// bf16 split weights for the layer-0 input projection GEMM
__device__ __nv_bfloat16 g_w0h[HH * DD], g_w0l[HH * DD];

// ---------------- split barrier ops -----------------------------------------
// arrive: non-blocking for the CTA (thread 0 does release + count).
__device__ __forceinline__ void bar_arrive(unsigned* cnt, unsigned* gen) {
    __syncthreads();                    // all threads' publishes issued
    if (threadIdx.x == 0) {
        __threadfence();                // release
        unsigned old = atomicAdd(cnt, 1u);
        if ((old & (GRP - 1u)) == GRP - 1u)
            atomicAdd(gen, 1u);         // group complete -> bump generation
    }
}
// wait: block until generation reaches target (acquire).
__device__ __forceinline__ void bar_wait(volatile unsigned* gen, unsigned tgt) {
    if (threadIdx.x == 0) {
        while (*gen < tgt) {}
        __threadfence();                // acquire
    }
    __syncthreads();
}

// ---------------- barrier reset (before each fused_rec launch) --------------
__global__ void reset_bars() {
    if (threadIdx.x < 8) {
        g_cseq[threadIdx.x] = 0u; g_gseq[threadIdx.x] = 0u;
        g_ch1[threadIdx.x]  = 0u; g_gh1[threadIdx.x]  = 0u;
    }
}

// ---------------- MMA plumbing ----------------------------------------------
__device__ __forceinline__ uint32_t s2u(const void* p) {
    uint32_t a;
    asm("{ .reg .u64 t; cvta.to.shared.u64 t, %1; cvt.u32.u64 %0, t; }"
        : "=r"(a) : "l"(p));
    return a;
}
__device__ __forceinline__ void ldm_x4(uint32_t& r0, uint32_t& r1,
                                       uint32_t& r2, uint32_t& r3,
                                       uint32_t addr) {
    asm volatile("ldmatrix.sync.aligned.m8n8.x4.shared.b16 {%0,%1,%2,%3}, [%4];"
                 : "=r"(r0), "=r"(r1), "=r"(r2), "=r"(r3) : "r"(addr));
}
__device__ __forceinline__ void ldm_x2(uint32_t& r0, uint32_t& r1,
                                       uint32_t addr) {
    asm volatile("ldmatrix.sync.aligned.m8n8.x2.shared.b16 {%0,%1}, [%2];"
                 : "=r"(r0), "=r"(r1) : "r"(addr));
}
__device__ __forceinline__ void mma_bf16(float* d, const uint32_t* a,
                                         uint32_t b0, uint32_t b1) {
    asm volatile(
        "mma.sync.aligned.m16n8k16.row.col.f32.bf16.bf16.f32 "
        "{%0,%1,%2,%3}, {%4,%5,%6,%7}, {%8,%9}, {%0,%1,%2,%3};"
        : "+f"(d[0]), "+f"(d[1]), "+f"(d[2]), "+f"(d[3])
        : "r"(a[0]), "r"(a[1]), "r"(a[2]), "r"(a[3]), "r"(b0), "r"(b1));
}
__device__ __forceinline__ void mma_f16(float* d, const uint32_t* a,
                                        uint32_t b0, uint32_t b1) {
    asm volatile(
        "mma.sync.aligned.m16n8k16.row.col.f32.f16.f16.f32 "
        "{%0,%1,%2,%3}, {%4,%5,%6,%7}, {%8,%9}, {%0,%1,%2,%3};"
        : "+f"(d[0]), "+f"(d[1]), "+f"(d[2]), "+f"(d[3])
        : "r"(a[0]), "r"(a[1]), "r"(a[2]), "r"(a[3]), "r"(b0), "r"(b1));
}
__device__ __forceinline__ uint32_t packsplit(float v) {
    __nv_bfloat16 h = __float2bfloat16(v);
    __nv_bfloat16 l = __float2bfloat16(v - __bfloat162float(h));
    return (uint32_t)__bfloat16_as_ushort(h) |
           ((uint32_t)__bfloat16_as_ushort(l) << 16);
}
__device__ __forceinline__ uint32_t packh2(float lo, float hi) {
    __half2 h = __floats2half2_rn(lo, hi);   // .x = lo (low 16 bits)
    uint32_t u;
    asm("mov.b32 %0, %1;" : "=r"(u) : "r"(*(uint32_t*)&h));
    return u;
}
__device__ __forceinline__ uint32_t packh2f4lo(float x, float y) {
    return (uint32_t)__half_as_ushort(__float2half_rn(x)) |
           ((uint32_t)__half_as_ushort(__float2half_rn(y)) << 16);
}
__device__ __forceinline__ float2 unpackh2(uint32_t u) {
    __half2 h = *(__half2*)&u;
    return __half22float2(h);
}

// ---------------- weight convert: fp32 -> bf16 hi/lo (layer-0 inproj) -------
__global__ void convert_w0(const float* __restrict__ w0) {
    int i = blockIdx.x * 256 + threadIdx.x;
    if (i < HH * DD) {
        float v = w0[i];
        __nv_bfloat16 h = __float2bfloat16(v);
        g_w0h[i] = h;
        g_w0l[i] = __float2bfloat16(v - __bfloat162float(h));
    }
}

// ---------------- HMMA GEMM: Cm(packed fp16) = A @ W^T + b1 + b2 ------------
// Split bf16: C = Ah*Wh + Ah*Wl + Al*Wh, fp32 accum. Output packed __half2.
#define HM_AH 0
#define HM_AL 8192
#define HM_WH 16384
#define HM_WL 24576
#define HM_SB 32768
#define HM_TOTAL (32768 + 512)

__global__ __launch_bounds__(256, 2) void gemm_hmma(
    const float* __restrict__ A,
    const __nv_bfloat16* __restrict__ Wh, const __nv_bfloat16* __restrict__ Wl,
    const float* __restrict__ b1, const float* __restrict__ b2,
    uint32_t* __restrict__ Cm, int K, int permute)
{
    __shared__ __align__(128) uint8_t sm[HM_TOTAL];
    uint32_t sbase = s2u(sm);

    int tid = threadIdx.x;
    int lane = tid & 31;
    int wid = tid >> 5;
    int wm = wid & 3;
    int wn = wid >> 2;
    int m0 = blockIdx.x * 128;
    int n0 = blockIdx.y * 128;

    if (tid < 128) {
        int n = n0 + tid;
        ((float*)(sm + HM_SB))[tid] = b1[n] + (b2 ? b2[n] : 0.f);
    }

    const float* Ap[4];
#pragma unroll
    for (int it = 0; it < 4; ++it) {
        int idx = tid + it * 256;
        int row = idx >> 3;
        int gm = m0 + row;
        if (permute) {
            int b_ = gm & (BB - 1);
            int t_ = gm >> 8;                  // BB == 256
            Ap[it] = A + ((size_t)b_ * TT + t_) * K;
        } else {
            Ap[it] = A + (size_t)gm * K;
        }
    }

    float acc[2][8][4];
#pragma unroll
    for (int mf = 0; mf < 2; ++mf)
#pragma unroll
        for (int nf = 0; nf < 8; ++nf)
#pragma unroll
            for (int q = 0; q < 4; ++q) acc[mf][nf][q] = 0.f;

    int sub = lane >> 3;
    int r8  = lane & 7;

    int nch = K >> 5;
    for (int c = 0; c < nch; ++c) {
        int kc = c << 5;
        __syncthreads();

#pragma unroll
        for (int it = 0; it < 4; ++it) {
            int idx = tid + it * 256;
            int row = idx >> 3, kq = idx & 7;
            float4 v = *(const float4*)(Ap[it] + kc + kq * 4);
            uint32_t s0 = packsplit(v.x), s1 = packsplit(v.y);
            uint32_t s2 = packsplit(v.z), s3 = packsplit(v.w);
            uint2 hp, lp;
            hp.x = (s0 & 0xffffu) | (s1 << 16);
            hp.y = (s2 & 0xffffu) | (s3 << 16);
            lp.x = (s0 >> 16) | (s1 & 0xffff0000u);
            lp.y = (s2 >> 16) | (s3 & 0xffff0000u);
            int kt = kq >> 1, kcol = (kq & 1) * 4;
            uint32_t off = (uint32_t)(((kt * 16) + (row >> 3)) * 128 +
                                      (row & 7) * 16 + kcol * 2);
            *(uint2*)(sm + HM_AH + off) = hp;
            *(uint2*)(sm + HM_AL + off) = lp;
        }
#pragma unroll
        for (int it = 0; it < 4; ++it) {
            int idx = tid + it * 256;
            int row = idx >> 3, kq = idx & 7;
            size_t go = (size_t)(n0 + row) * K + kc + kq * 4;
            uint2 hv = *(const uint2*)(Wh + go);
            uint2 lv = *(const uint2*)(Wl + go);
            int kt = kq >> 1, kcol = (kq & 1) * 4;
            uint32_t off = (uint32_t)(((kt * 16) + (row >> 3)) * 128 +
                                      (row & 7) * 16 + kcol * 2);
            *(uint2*)(sm + HM_WH + off) = hv;
            *(uint2*)(sm + HM_WL + off) = lv;
        }
        __syncthreads();

#pragma unroll
        for (int s = 0; s < 2; ++s) {
            uint32_t ah[2][4], al[2][4];
#pragma unroll
            for (int mf = 0; mf < 2; ++mf) {
                int mt = wm * 4 + mf * 2 + (sub & 1);
                int kt = s * 2 + (sub >> 1);
                uint32_t ad = sbase + HM_AH +
                              (uint32_t)(((kt * 16) + mt) * 128 + r8 * 16);
                ldm_x4(ah[mf][0], ah[mf][1], ah[mf][2], ah[mf][3], ad);
                ldm_x4(al[mf][0], al[mf][1], al[mf][2], al[mf][3],
                       ad + (HM_AL - HM_AH));
            }
#pragma unroll
            for (int nf = 0; nf < 8; ++nf) {
                int nt = wn * 8 + nf;
                int ktb = s * 2 + (sub & 1);
                uint32_t bd = sbase + HM_WH +
                              (uint32_t)(((ktb * 16) + nt) * 128 + r8 * 16);
                uint32_t bh0, bh1, bl0, bl1;
                ldm_x2(bh0, bh1, bd);
                ldm_x2(bl0, bl1, bd + (HM_WL - HM_WH));
                mma_bf16(acc[0][nf], ah[0], bh0, bh1);
                mma_bf16(acc[1][nf], ah[1], bh0, bh1);
                mma_bf16(acc[0][nf], ah[0], bl0, bl1);
                mma_bf16(acc[1][nf], ah[1], bl0, bl1);
                mma_bf16(acc[0][nf], al[0], bh0, bh1);
                mma_bf16(acc[1][nf], al[1], bh0, bh1);
            }
        }
    }

    const float* sb = (const float*)(sm + HM_SB);
#pragma unroll
    for (int mf = 0; mf < 2; ++mf) {
        int mrow = m0 + wm * 32 + mf * 16 + (lane >> 2);
#pragma unroll
        for (int nf = 0; nf < 8; ++nf) {
            int ncol = wn * 64 + nf * 8 + (lane & 3) * 2;
            float bb0 = sb[ncol], bb1 = sb[ncol + 1];
            int gc = (n0 + ncol) >> 1;
            Cm[(size_t)mrow * HW + gc] =
                packh2(acc[mf][nf][0] + bb0, acc[mf][nf][1] + bb1);
            Cm[(size_t)(mrow + 8) * HW + gc] =
                packh2(acc[mf][nf][2] + bb0, acc[mf][nf][3] + bb1);
        }
    }
}

// ---------------- fused dual-layer persistent recurrence (fp16) -------------
// Superstep s (0..TT):
//   seq0[s]  = relu(xp0[s] + seq0[s-1] @ W0hh^T)                (s <= TT-1)
//   h1[s-1]  = relu(seq0[s-1] @ W1ih^T + b1 + h1[s-2] @ W1hh^T) (s >= 1)
// Split arrive/wait barriers: seq0 is published + arrived right after
// phase 1, so the zero-slack seq0 chain excludes phase 2 and both barrier
// rendezvous latencies are overlapped with off-chain work.
// A/W layout: kb*512 stride, XOR swizzle by kb&7 (R9-proven addressing).
#define FS_W0 0
#define FS_W1 32768
#define FS_WI 65536
#define FS_A1 98304
#define FS_A2 131072
#define FS_TOTAL 163840

__global__ __launch_bounds__(256, 1) void fused_rec(
    const uint32_t* __restrict__ xp0,  // [T][B][HW] fp16 pairs
    const float* __restrict__ W0hh,    // [H][H] fp32
    const float* __restrict__ W1hh,    // [H][H] fp32
    const float* __restrict__ W1ih,    // [H][H] fp32
    const float* __restrict__ b_ih1,
    const float* __restrict__ b_hh1,
    uint32_t* __restrict__ s0ring,     // [2][B][HW] fp16 pairs
    uint32_t* __restrict__ h1ring,     // [2][B][HW] fp16 pairs
    float* __restrict__ h_last)        // [B][H] fp32
{
    extern __shared__ uint8_t sm[];
    uint32_t sb = s2u(sm);

    int cid = blockIdx.x;
    int bt = cid >> 4;                 // 0..7
    int jt = cid & 15;                 // 0..15
    int b0 = bt * 32, j0 = jt * 32;

    int tid = threadIdx.x;
    int lane = tid & 31, wid = tid >> 5;
    int sub = lane >> 3, r8 = lane & 7;
    int mt = wid & 1;                  // 16-row m-tile
    int jb = wid >> 1;                 // 8-col j-block (0..3)

    // ---- preload weight slices (one time): single fp16 --------------------
    for (int idx = tid; idx < 4096; idx += 256) {
        int row = idx >> 7, kq = idx & 127;
        int kb = kq >> 1;
        uint32_t off = (uint32_t)kb * 512u + (uint32_t)(row >> 3) * 128u +
                       ((uint32_t)((row & 7) ^ (kb & 7)) << 4) +
                       (uint32_t)(kq & 1) * 8u;
        {
            float4 v = *(const float4*)(W0hh + (size_t)(j0 + row) * HH + kq * 4);
            uint2 w;
            w.x = packh2f4lo(v.x, v.y);
            w.y = packh2f4lo(v.z, v.w);
            *(uint2*)(sm + FS_W0 + off) = w;
        }
        {
            float4 v = *(const float4*)(W1hh + (size_t)(j0 + row) * HH + kq * 4);
            uint2 w;
            w.x = packh2f4lo(v.x, v.y);
            w.y = packh2f4lo(v.z, v.w);
            *(uint2*)(sm + FS_W1 + off) = w;
        }
        {
            float4 v = *(const float4*)(W1ih + (size_t)(j0 + row) * HH + kq * 4);
            uint2 w;
            w.x = packh2f4lo(v.x, v.y);
            w.y = packh2f4lo(v.z, v.w);
            *(uint2*)(sm + FS_WI + off) = w;
        }
    }

    // output fragment coordinates (m16n8 D layout)
    int brow = b0 + mt * 16 + (lane >> 2);
    int jcol = j0 + jb * 8 + (lane & 3) * 2;

    float2 bias1;
    bias1.x = b_ih1[jcol] + b_hh1[jcol];
    bias1.y = b_ih1[jcol + 1] + b_hh1[jcol + 1];

    __syncthreads();   // weights visible CTA-wide

    for (int s = 0; s <= TT; ++s) {
        const int doL0 = (s < TT);
        const int haveA = (s >= 1);
        const int doHH = (s >= 2);

        float acc0[4] = {0.f, 0.f, 0.f, 0.f};
        float accx[4] = {0.f, 0.f, 0.f, 0.f};

        // ---- prefetch xp0[s] (packed) — barrier-independent ---------------
        uint32_t xa = 0u, xb = 0u;
        if (doL0) {
            const uint32_t* xpt = xp0 + (size_t)s * BB * HW;
            xa = xpt[(size_t)brow * HW + (jcol >> 1)];
            xb = xpt[(size_t)(brow + 8) * HW + (jcol >> 1)];
        }

        if (haveA) {
            // ---- wait for seq0[s-1] (arrived mid-superstep s-1 -> ~free) --
            bar_wait(&g_gseq[bt], (unsigned)s);

            // ---- stage A1 (seq0[s-1]) -> smem -----------------------------
            {
                const uint32_t* hsrc = s0ring + (size_t)((s - 1) & 1) * BB * HW;
#pragma unroll
                for (int it = 0; it < 8; ++it) {
                    int idx = tid + it * 256;
                    int row = idx >> 6, kb = idx & 63;
                    uint4 p = *(const uint4*)(hsrc + (size_t)(b0 + row) * HW +
                                              kb * 4);
                    uint32_t off = (uint32_t)kb * 512u +
                                   (uint32_t)(row >> 3) * 128u +
                                   ((uint32_t)((row & 7) ^ (kb & 7)) << 4);
                    *(uint4*)(sm + FS_A1 + off) = p;
                }
            }
            __syncthreads();   // A1 visible

            // ---- phase 1: acc0 += A1@W0hh, accx += A1@W1ih ----------------
#pragma unroll 4
            for (int ks = 0; ks < 32; ++ks) {
                int kbA = ks * 2 + (sub >> 1);
                uint32_t aoff = (uint32_t)kbA * 512u +
                                (uint32_t)(mt * 2 + (sub & 1)) * 128u +
                                ((uint32_t)(r8 ^ (kbA & 7)) << 4);
                uint32_t a1[4];
                ldm_x4(a1[0], a1[1], a1[2], a1[3], sb + FS_A1 + aoff);

                int kbB = ks * 2 + (sub & 1);
                uint32_t boff = (uint32_t)kbB * 512u + (uint32_t)jb * 128u +
                                ((uint32_t)(r8 ^ (kbB & 7)) << 4);
                uint32_t w00, w01, wi0, wi1;
                ldm_x2(w00, w01, sb + FS_W0 + boff);
                ldm_x2(wi0, wi1, sb + FS_WI + boff);

                if (doL0) mma_f16(acc0, a1, w00, w01);
                mma_f16(accx, a1, wi0, wi1);
            }
        }

        // ---- publish seq0[s] + EARLY seq barrier arrive -------------------
        if (doL0) {
            float2 x0 = unpackh2(xa);
            float2 x1 = unpackh2(xb);
            float v0 = fmaxf(acc0[0] + x0.x, 0.f);
            float v1 = fmaxf(acc0[1] + x0.y, 0.f);
            float v2 = fmaxf(acc0[2] + x1.x, 0.f);
            float v3 = fmaxf(acc0[3] + x1.y, 0.f);
            uint32_t* hdst = s0ring + (size_t)(s & 1) * BB * HW;
            hdst[(size_t)brow * HW + (jcol >> 1)] = packh2(v0, v1);
            hdst[(size_t)(brow + 8) * HW + (jcol >> 1)] = packh2(v2, v3);
            bar_arrive(&g_cseq[bt], &g_gseq[bt]);   // syncthreads inside
        }

        // ---- phase 2: accx += h1[s-2] @ W1hh ------------------------------
        if (doHH) {
            // wait for h1[s-2] (arrived end of superstep s-1 -> mostly free)
            bar_wait(&g_gh1[bt], (unsigned)(s - 1));

            const uint32_t* hsrc = h1ring + (size_t)(s & 1) * BB * HW;
#pragma unroll
            for (int it = 0; it < 8; ++it) {
                int idx = tid + it * 256;
                int row = idx >> 6, kb = idx & 63;
                uint4 p = *(const uint4*)(hsrc + (size_t)(b0 + row) * HW +
                                          kb * 4);
                uint32_t off = (uint32_t)kb * 512u +
                               (uint32_t)(row >> 3) * 128u +
                               ((uint32_t)((row & 7) ^ (kb & 7)) << 4);
                *(uint4*)(sm + FS_A2 + off) = p;
            }
            __syncthreads();   // A2 visible

#pragma unroll 4
            for (int ks = 0; ks < 32; ++ks) {
                int kbA = ks * 2 + (sub >> 1);
                uint32_t aoff = (uint32_t)kbA * 512u +
                                (uint32_t)(mt * 2 + (sub & 1)) * 128u +
                                ((uint32_t)(r8 ^ (kbA & 7)) << 4);
                uint32_t a2[4];
                ldm_x4(a2[0], a2[1], a2[2], a2[3], sb + FS_A2 + aoff);

                int kbB = ks * 2 + (sub & 1);
                uint32_t boff = (uint32_t)kbB * 512u + (uint32_t)jb * 128u +
                                ((uint32_t)(r8 ^ (kbB & 7)) << 4);
                uint32_t w10, w11;
                ldm_x2(w10, w11, sb + FS_W1 + boff);
                mma_f16(accx, a2, w10, w11);
            }
        }

        // ---- publish h1[s-1] + h1 barrier arrive --------------------------
        if (haveA) {
            float v0 = fmaxf(accx[0] + bias1.x, 0.f);
            float v1 = fmaxf(accx[1] + bias1.y, 0.f);
            float v2 = fmaxf(accx[2] + bias1.x, 0.f);
            float v3 = fmaxf(accx[3] + bias1.y, 0.f);
            uint32_t* hdst = h1ring + (size_t)((s - 1) & 1) * BB * HW;
            hdst[(size_t)brow * HW + (jcol >> 1)] = packh2(v0, v1);
            hdst[(size_t)(brow + 8) * HW + (jcol >> 1)] = packh2(v2, v3);
            if (s - 1 == TT - 1) {
                *(float2*)(h_last + (size_t)brow * HH + jcol) =
                    make_float2(v0, v1);
                *(float2*)(h_last + (size_t)(brow + 8) * HH + jcol) =
                    make_float2(v2, v3);
            }
            bar_arrive(&g_ch1[bt], &g_gh1[bt]);     // syncthreads inside
        }
    }
}

// ---------------- head: relu(h @ fc1^T + b1) @ fc2^T + b2 -------------------
__global__ __launch_bounds__(256) void head_kernel(
    const float* __restrict__ hl, const float* __restrict__ w1,
    const float* __restrict__ b1f, const float* __restrict__ w2,
    const float* __restrict__ b2f, float* __restrict__ out)
{
    __shared__ float sh[8];
    int b = blockIdx.x;
    int tid = threadIdx.x;
    int w = tid >> 5;
    int lane = tid & 31;

    const float* hb = hl + (size_t)b * HH;
    const float* wr = w1 + (size_t)w * HH;
    float ssum = 0.f;
    for (int k = lane; k < HH; k += 32) ssum += hb[k] * wr[k];
#pragma unroll
    for (int o = 16; o; o >>= 1) ssum += __shfl_xor_sync(0xffffffffu, ssum, o);
    if (lane == 0) sh[w] = fmaxf(ssum + b1f[w], 0.f);
    __syncthreads();
    if (tid < OO) {
        float r = b2f[tid];
#pragma unroll
        for (int j = 0; j < 8; ++j) r += sh[j] * w2[tid * 8 + j];
        out[(size_t)b * OO + tid] = r;
    }
}

// ---------------- launch ----------------------------------------------------
extern "C" void kernel_launch(void* const* d_in, const int* in_sizes, int n_in,
                              void* d_out, int out_size)
{
    const float* x     = (const float*)d_in[0];
    const float* w_ih0 = (const float*)d_in[1];
    const float* w_hh0 = (const float*)d_in[2];
    const float* b_ih0 = (const float*)d_in[3];
    const float* b_hh0 = (const float*)d_in[4];
    const float* w_ih1 = (const float*)d_in[5];
    const float* w_hh1 = (const float*)d_in[6];
    const float* b_ih1 = (const float*)d_in[7];
    const float* b_hh1 = (const float*)d_in[8];
    const float* fc1_w = (const float*)d_in[9];
    const float* fc1_b = (const float*)d_in[10];
    const float* fc2_w = (const float*)d_in[11];
    const float* fc2_b = (const float*)d_in[12];
    float* out = (float*)d_out;

    void* p;
    cudaGetSymbolAddress(&p, g_xp0);   uint32_t* xp0 = (uint32_t*)p;
    cudaGetSymbolAddress(&p, g_s0);    uint32_t* s0ring = (uint32_t*)p;
    cudaGetSymbolAddress(&p, g_h1);    uint32_t* h1ring = (uint32_t*)p;
    cudaGetSymbolAddress(&p, g_hlast); float* hlast = (float*)p;
    cudaGetSymbolAddress(&p, g_w0h);   __nv_bfloat16* w0h = (__nv_bfloat16*)p;
    cudaGetSymbolAddress(&p, g_w0l);   __nv_bfloat16* w0l = (__nv_bfloat16*)p;

    cudaFuncSetAttribute(fused_rec,
                         cudaFuncAttributeMaxDynamicSharedMemorySize,
                         FS_TOTAL);

    dim3 gg(TT * BB / 128, HH / 128);   // 512 x 4

    // layer-0 input projection weights -> bf16 hi/lo
    convert_w0<<<(HH * DD + 255) / 256, 256>>>(w_ih0);
    // layer-0 input projection: xp0 = x @ w_ih0^T + b_ih0 + b_hh0 (fp16 out)
    gemm_hmma<<<gg, 256>>>(x, w0h, w0l, b_ih0, b_hh0, xp0, DD, 1);
    // reset split barriers, then fused dual-layer recurrence
    reset_bars<<<1, 32>>>();
    fused_rec<<<NBLK, 256, FS_TOTAL>>>(xp0, w_hh0, w_hh1, w_ih1,
                                       b_ih1, b_hh1, s0ring, h1ring, hlast);
    // head
    head_kernel<<<BB, 256>>>(hlast, fc1_w, fc1_b, fc2_w, fc2_b, out);
}

// round 17
// speedup vs baseline: 1.5095x; 1.5095x over previous
#include <cuda_runtime.h>
#include <cuda_bf16.h>
#include <cuda_fp16.h>
#include <cstdint>

#define BB 256     // batch
#define TT 256     // time steps
#define DD 64      // input dim
#define HH 512     // hidden
#define OO 10      // output classes

#define NBLK 128   // fused rec grid: 8 bt x 16 jt (all co-resident, 1/SM)
#define GRP  16    // CTAs per bt dependency group
#define HW   (HH / 2)   // packed fp16-pair row stride (uint32 units)

// ---------------- scratch (static device globals; no allocation allowed) ----
__device__ uint32_t g_xp0[TT * BB * HW];     // [t][b][h/2] fp16 pairs
__device__ uint32_t g_s0[2][BB * HW];        // seq0 ring, fp16 pairs
__device__ uint32_t g_h1[2][BB * HW];        // layer-1 h ring, fp16 pairs
__device__ float    g_hlast[BB * HH];

// monotonic arrival counters, one per bt group (reset before each launch)
__device__ __align__(128) unsigned g_cnt[8];

// bf16 split weights for the layer-0 input projection GEMM
__device__ __nv_bfloat16 g_w0h[HH * DD], g_w0l[HH * DD];

// ---------------- fence-free monotonic barrier ------------------------------
// arrive with release semantics folded into the reduction; poll with acquire
// loads. No membar.gpu, no generation variable, no releaser role.
__device__ __forceinline__ void grp_bar(int bt, unsigned tgt) {
    __syncthreads();                   // all threads' publishes issued
    if (threadIdx.x == 0) {
        asm volatile("red.release.gpu.global.add.u32 [%0], 1;"
                     :: "l"(&g_cnt[bt]) : "memory");
        unsigned v;
        do {
            asm volatile("ld.acquire.gpu.global.u32 %0, [%1];"
                         : "=r"(v) : "l"(&g_cnt[bt]) : "memory");
        } while (v < tgt);
    }
    __syncthreads();
}

// ---------------- counter reset (before each fused_rec launch) --------------
__global__ void reset_bars() {
    if (threadIdx.x < 8) g_cnt[threadIdx.x] = 0u;
}

// ---------------- MMA plumbing ----------------------------------------------
__device__ __forceinline__ uint32_t s2u(const void* p) {
    uint32_t a;
    asm("{ .reg .u64 t; cvta.to.shared.u64 t, %1; cvt.u32.u64 %0, t; }"
        : "=r"(a) : "l"(p));
    return a;
}
__device__ __forceinline__ void ldm_x4(uint32_t& r0, uint32_t& r1,
                                       uint32_t& r2, uint32_t& r3,
                                       uint32_t addr) {
    asm volatile("ldmatrix.sync.aligned.m8n8.x4.shared.b16 {%0,%1,%2,%3}, [%4];"
                 : "=r"(r0), "=r"(r1), "=r"(r2), "=r"(r3) : "r"(addr));
}
__device__ __forceinline__ void ldm_x2(uint32_t& r0, uint32_t& r1,
                                       uint32_t addr) {
    asm volatile("ldmatrix.sync.aligned.m8n8.x2.shared.b16 {%0,%1}, [%2];"
                 : "=r"(r0), "=r"(r1) : "r"(addr));
}
__device__ __forceinline__ void mma_bf16(float* d, const uint32_t* a,
                                         uint32_t b0, uint32_t b1) {
    asm volatile(
        "mma.sync.aligned.m16n8k16.row.col.f32.bf16.bf16.f32 "
        "{%0,%1,%2,%3}, {%4,%5,%6,%7}, {%8,%9}, {%0,%1,%2,%3};"
        : "+f"(d[0]), "+f"(d[1]), "+f"(d[2]), "+f"(d[3])
        : "r"(a[0]), "r"(a[1]), "r"(a[2]), "r"(a[3]), "r"(b0), "r"(b1));
}
__device__ __forceinline__ void mma_f16(float* d, const uint32_t* a,
                                        uint32_t b0, uint32_t b1) {
    asm volatile(
        "mma.sync.aligned.m16n8k16.row.col.f32.f16.f16.f32 "
        "{%0,%1,%2,%3}, {%4,%5,%6,%7}, {%8,%9}, {%0,%1,%2,%3};"
        : "+f"(d[0]), "+f"(d[1]), "+f"(d[2]), "+f"(d[3])
        : "r"(a[0]), "r"(a[1]), "r"(a[2]), "r"(a[3]), "r"(b0), "r"(b1));
}
__device__ __forceinline__ uint32_t packsplit(float v) {
    __nv_bfloat16 h = __float2bfloat16(v);
    __nv_bfloat16 l = __float2bfloat16(v - __bfloat162float(h));
    return (uint32_t)__bfloat16_as_ushort(h) |
           ((uint32_t)__bfloat16_as_ushort(l) << 16);
}
__device__ __forceinline__ uint32_t packh2(float lo, float hi) {
    __half2 h = __floats2half2_rn(lo, hi);   // .x = lo (low 16 bits)
    uint32_t u;
    asm("mov.b32 %0, %1;" : "=r"(u) : "r"(*(uint32_t*)&h));
    return u;
}
__device__ __forceinline__ uint32_t packh2f4lo(float x, float y) {
    return (uint32_t)__half_as_ushort(__float2half_rn(x)) |
           ((uint32_t)__half_as_ushort(__float2half_rn(y)) << 16);
}
__device__ __forceinline__ float2 unpackh2(uint32_t u) {
    __half2 h = *(__half2*)&u;
    return __half22float2(h);
}

// ---------------- weight convert: fp32 -> bf16 hi/lo (layer-0 inproj) -------
__global__ void convert_w0(const float* __restrict__ w0) {
    int i = blockIdx.x * 256 + threadIdx.x;
    if (i < HH * DD) {
        float v = w0[i];
        __nv_bfloat16 h = __float2bfloat16(v);
        g_w0h[i] = h;
        g_w0l[i] = __float2bfloat16(v - __bfloat162float(h));
    }
}

// ---------------- HMMA GEMM: Cm(packed fp16) = A @ W^T + b1 + b2 ------------
// Split bf16: C = Ah*Wh + Ah*Wl + Al*Wh, fp32 accum. Output packed __half2.
#define HM_AH 0
#define HM_AL 8192
#define HM_WH 16384
#define HM_WL 24576
#define HM_SB 32768
#define HM_TOTAL (32768 + 512)

__global__ __launch_bounds__(256, 2) void gemm_hmma(
    const float* __restrict__ A,
    const __nv_bfloat16* __restrict__ Wh, const __nv_bfloat16* __restrict__ Wl,
    const float* __restrict__ b1, const float* __restrict__ b2,
    uint32_t* __restrict__ Cm, int K, int permute)
{
    __shared__ __align__(128) uint8_t sm[HM_TOTAL];
    uint32_t sbase = s2u(sm);

    int tid = threadIdx.x;
    int lane = tid & 31;
    int wid = tid >> 5;
    int wm = wid & 3;
    int wn = wid >> 2;
    int m0 = blockIdx.x * 128;
    int n0 = blockIdx.y * 128;

    if (tid < 128) {
        int n = n0 + tid;
        ((float*)(sm + HM_SB))[tid] = b1[n] + (b2 ? b2[n] : 0.f);
    }

    const float* Ap[4];
#pragma unroll
    for (int it = 0; it < 4; ++it) {
        int idx = tid + it * 256;
        int row = idx >> 3;
        int gm = m0 + row;
        if (permute) {
            int b_ = gm & (BB - 1);
            int t_ = gm >> 8;                  // BB == 256
            Ap[it] = A + ((size_t)b_ * TT + t_) * K;
        } else {
            Ap[it] = A + (size_t)gm * K;
        }
    }

    float acc[2][8][4];
#pragma unroll
    for (int mf = 0; mf < 2; ++mf)
#pragma unroll
        for (int nf = 0; nf < 8; ++nf)
#pragma unroll
            for (int q = 0; q < 4; ++q) acc[mf][nf][q] = 0.f;

    int sub = lane >> 3;
    int r8  = lane & 7;

    int nch = K >> 5;
    for (int c = 0; c < nch; ++c) {
        int kc = c << 5;
        __syncthreads();

#pragma unroll
        for (int it = 0; it < 4; ++it) {
            int idx = tid + it * 256;
            int row = idx >> 3, kq = idx & 7;
            float4 v = *(const float4*)(Ap[it] + kc + kq * 4);
            uint32_t s0 = packsplit(v.x), s1 = packsplit(v.y);
            uint32_t s2 = packsplit(v.z), s3 = packsplit(v.w);
            uint2 hp, lp;
            hp.x = (s0 & 0xffffu) | (s1 << 16);
            hp.y = (s2 & 0xffffu) | (s3 << 16);
            lp.x = (s0 >> 16) | (s1 & 0xffff0000u);
            lp.y = (s2 >> 16) | (s3 & 0xffff0000u);
            int kt = kq >> 1, kcol = (kq & 1) * 4;
            uint32_t off = (uint32_t)(((kt * 16) + (row >> 3)) * 128 +
                                      (row & 7) * 16 + kcol * 2);
            *(uint2*)(sm + HM_AH + off) = hp;
            *(uint2*)(sm + HM_AL + off) = lp;
        }
#pragma unroll
        for (int it = 0; it < 4; ++it) {
            int idx = tid + it * 256;
            int row = idx >> 3, kq = idx & 7;
            size_t go = (size_t)(n0 + row) * K + kc + kq * 4;
            uint2 hv = *(const uint2*)(Wh + go);
            uint2 lv = *(const uint2*)(Wl + go);
            int kt = kq >> 1, kcol = (kq & 1) * 4;
            uint32_t off = (uint32_t)(((kt * 16) + (row >> 3)) * 128 +
                                      (row & 7) * 16 + kcol * 2);
            *(uint2*)(sm + HM_WH + off) = hv;
            *(uint2*)(sm + HM_WL + off) = lv;
        }
        __syncthreads();

#pragma unroll
        for (int s = 0; s < 2; ++s) {
            uint32_t ah[2][4], al[2][4];
#pragma unroll
            for (int mf = 0; mf < 2; ++mf) {
                int mt = wm * 4 + mf * 2 + (sub & 1);
                int kt = s * 2 + (sub >> 1);
                uint32_t ad = sbase + HM_AH +
                              (uint32_t)(((kt * 16) + mt) * 128 + r8 * 16);
                ldm_x4(ah[mf][0], ah[mf][1], ah[mf][2], ah[mf][3], ad);
                ldm_x4(al[mf][0], al[mf][1], al[mf][2], al[mf][3],
                       ad + (HM_AL - HM_AH));
            }
#pragma unroll
            for (int nf = 0; nf < 8; ++nf) {
                int nt = wn * 8 + nf;
                int ktb = s * 2 + (sub & 1);
                uint32_t bd = sbase + HM_WH +
                              (uint32_t)(((ktb * 16) + nt) * 128 + r8 * 16);
                uint32_t bh0, bh1, bl0, bl1;
                ldm_x2(bh0, bh1, bd);
                ldm_x2(bl0, bl1, bd + (HM_WL - HM_WH));
                mma_bf16(acc[0][nf], ah[0], bh0, bh1);
                mma_bf16(acc[1][nf], ah[1], bh0, bh1);
                mma_bf16(acc[0][nf], ah[0], bl0, bl1);
                mma_bf16(acc[1][nf], ah[1], bl0, bl1);
                mma_bf16(acc[0][nf], al[0], bh0, bh1);
                mma_bf16(acc[1][nf], al[1], bh0, bh1);
            }
        }
    }

    const float* sb = (const float*)(sm + HM_SB);
#pragma unroll
    for (int mf = 0; mf < 2; ++mf) {
        int mrow = m0 + wm * 32 + mf * 16 + (lane >> 2);
#pragma unroll
        for (int nf = 0; nf < 8; ++nf) {
            int ncol = wn * 64 + nf * 8 + (lane & 3) * 2;
            float bb0 = sb[ncol], bb1 = sb[ncol + 1];
            int gc = (n0 + ncol) >> 1;
            Cm[(size_t)mrow * HW + gc] =
                packh2(acc[mf][nf][0] + bb0, acc[mf][nf][1] + bb1);
            Cm[(size_t)(mrow + 8) * HW + gc] =
                packh2(acc[mf][nf][2] + bb0, acc[mf][nf][3] + bb1);
        }
    }
}

// ---------------- fused dual-layer persistent recurrence (fp16) -------------
// Superstep s (0..TT):
//   seq0[s]  = relu(xp0[s] + seq0[s-1] @ W0hh^T)                (s <= TT-1)
//   h1[s-1]  = relu(seq0[s-1] @ W1ih^T + b1 + h1[s-2] @ W1hh^T) (s >= 1)
// R15 structure (single barrier, split-staged A2) + fence-free barrier +
// merged W0/WI ldmatrix (lanes 0-15 -> W0 rows, lanes 16-31 -> WI rows).
// A/W layout: kb*512 stride, XOR swizzle by kb&7 (R9-proven addressing).
#define FS_W0 0
#define FS_W1 32768
#define FS_WI 65536
#define FS_A1 98304
#define FS_A2 131072
#define FS_TOTAL 163840

__global__ __launch_bounds__(256, 1) void fused_rec(
    const uint32_t* __restrict__ xp0,  // [T][B][HW] fp16 pairs
    const float* __restrict__ W0hh,    // [H][H] fp32
    const float* __restrict__ W1hh,    // [H][H] fp32
    const float* __restrict__ W1ih,    // [H][H] fp32
    const float* __restrict__ b_ih1,
    const float* __restrict__ b_hh1,
    uint32_t* __restrict__ s0ring,     // [2][B][HW] fp16 pairs
    uint32_t* __restrict__ h1ring,     // [2][B][HW] fp16 pairs
    float* __restrict__ h_last)        // [B][H] fp32
{
    extern __shared__ uint8_t sm[];
    uint32_t sb = s2u(sm);

    int cid = blockIdx.x;
    int bt = cid >> 4;                 // 0..7
    int jt = cid & 15;                 // 0..15
    int b0 = bt * 32, j0 = jt * 32;

    int tid = threadIdx.x;
    int lane = tid & 31, wid = tid >> 5;
    int sub = lane >> 3, r8 = lane & 7;
    int mt = wid & 1;                  // 16-row m-tile
    int jb = wid >> 1;                 // 8-col j-block (0..3)

    // ---- preload weight slices (one time): single fp16 --------------------
    for (int idx = tid; idx < 4096; idx += 256) {
        int row = idx >> 7, kq = idx & 127;
        int kb = kq >> 1;
        uint32_t off = (uint32_t)kb * 512u + (uint32_t)(row >> 3) * 128u +
                       ((uint32_t)((row & 7) ^ (kb & 7)) << 4) +
                       (uint32_t)(kq & 1) * 8u;
        {
            float4 v = *(const float4*)(W0hh + (size_t)(j0 + row) * HH + kq * 4);
            uint2 w;
            w.x = packh2f4lo(v.x, v.y);
            w.y = packh2f4lo(v.z, v.w);
            *(uint2*)(sm + FS_W0 + off) = w;
        }
        {
            float4 v = *(const float4*)(W1hh + (size_t)(j0 + row) * HH + kq * 4);
            uint2 w;
            w.x = packh2f4lo(v.x, v.y);
            w.y = packh2f4lo(v.z, v.w);
            *(uint2*)(sm + FS_W1 + off) = w;
        }
        {
            float4 v = *(const float4*)(W1ih + (size_t)(j0 + row) * HH + kq * 4);
            uint2 w;
            w.x = packh2f4lo(v.x, v.y);
            w.y = packh2f4lo(v.z, v.w);
            *(uint2*)(sm + FS_WI + off) = w;
        }
    }

    // output fragment coordinates (m16n8 D layout)
    int brow = b0 + mt * 16 + (lane >> 2);
    int jcol = j0 + jb * 8 + (lane & 3) * 2;

    // merged-W base: lanes 0-15 read W0, lanes 16-31 read WI (same geometry)
    uint32_t wmerge_base = sb + ((lane & 16) ? FS_WI : FS_W0);

    float2 bias1;
    bias1.x = b_ih1[jcol] + b_hh1[jcol];
    bias1.y = b_ih1[jcol + 1] + b_hh1[jcol + 1];

    __syncthreads();   // weights visible CTA-wide

    for (int s = 0; s <= TT; ++s) {
        const int doL0 = (s < TT);
        const int haveA = (s >= 1);
        const int doHH = (s >= 2);

        float acc0[4] = {0.f, 0.f, 0.f, 0.f};
        float accx[4] = {0.f, 0.f, 0.f, 0.f};

        // ---- prefetch xp0[s] (packed) — barrier-independent ---------------
        uint32_t xa = 0u, xb = 0u;
        if (doL0) {
            const uint32_t* xpt = xp0 + (size_t)s * BB * HW;
            xa = xpt[(size_t)brow * HW + (jcol >> 1)];
            xb = xpt[(size_t)(brow + 8) * HW + (jcol >> 1)];
        }

        if (haveA) {
            // ---- stage A1 (seq0[s-1]) to smem ----------------------------
            {
                const uint32_t* hsrc = s0ring + (size_t)((s - 1) & 1) * BB * HW;
#pragma unroll
                for (int it = 0; it < 8; ++it) {
                    int idx = tid + it * 256;
                    int row = idx >> 6, kb = idx & 63;
                    uint4 p = *(const uint4*)(hsrc + (size_t)(b0 + row) * HW +
                                              kb * 4);
                    uint32_t off = (uint32_t)kb * 512u +
                                   (uint32_t)(row >> 3) * 128u +
                                   ((uint32_t)((row & 7) ^ (kb & 7)) << 4);
                    *(uint4*)(sm + FS_A1 + off) = p;
                }
            }
            // ---- LDG A2 (h1[s-2]) into regs (latency hidden by phase 1) --
            uint4 a2r[8];
            if (doHH) {
                const uint32_t* hsrc = h1ring + (size_t)(s & 1) * BB * HW;
#pragma unroll
                for (int it = 0; it < 8; ++it) {
                    int idx = tid + it * 256;
                    int row = idx >> 6, kb = idx & 63;
                    a2r[it] = *(const uint4*)(hsrc + (size_t)(b0 + row) * HW +
                                              kb * 4);
                }
            }
            __syncthreads();   // A1 visible

            // ---- phase 1: acc0 += A1@W0hh, accx += A1@W1ih ---------------
            // merged ldm_x4: {w00,w01} from W0 (lanes 0-15),
            //                {wi0,wi1} from WI (lanes 16-31)
#pragma unroll 4
            for (int ks = 0; ks < 32; ++ks) {
                int kbA = ks * 2 + (sub >> 1);
                uint32_t aoff = (uint32_t)kbA * 512u +
                                (uint32_t)(mt * 2 + (sub & 1)) * 128u +
                                ((uint32_t)(r8 ^ (kbA & 7)) << 4);
                uint32_t a1[4];
                ldm_x4(a1[0], a1[1], a1[2], a1[3], sb + FS_A1 + aoff);

                int kbB = ks * 2 + (sub & 1);
                uint32_t boff = (uint32_t)kbB * 512u + (uint32_t)jb * 128u +
                                ((uint32_t)(r8 ^ (kbB & 7)) << 4);
                uint32_t w00, w01, wi0, wi1;
                ldm_x4(w00, w01, wi0, wi1, wmerge_base + boff);

                if (doL0) mma_f16(acc0, a1, w00, w01);
                mma_f16(accx, a1, wi0, wi1);
            }

            // ---- STS A2 + phase 2: accx += A2@W1hh -----------------------
            if (doHH) {
#pragma unroll
                for (int it = 0; it < 8; ++it) {
                    int idx = tid + it * 256;
                    int row = idx >> 6, kb = idx & 63;
                    uint32_t off = (uint32_t)kb * 512u +
                                   (uint32_t)(row >> 3) * 128u +
                                   ((uint32_t)((row & 7) ^ (kb & 7)) << 4);
                    *(uint4*)(sm + FS_A2 + off) = a2r[it];
                }
            }
            __syncthreads();   // A2 visible (and A1 reads complete)

            if (doHH) {
#pragma unroll 4
                for (int ks = 0; ks < 32; ++ks) {
                    int kbA = ks * 2 + (sub >> 1);
                    uint32_t aoff = (uint32_t)kbA * 512u +
                                    (uint32_t)(mt * 2 + (sub & 1)) * 128u +
                                    ((uint32_t)(r8 ^ (kbA & 7)) << 4);
                    uint32_t a2[4];
                    ldm_x4(a2[0], a2[1], a2[2], a2[3], sb + FS_A2 + aoff);

                    int kbB = ks * 2 + (sub & 1);
                    uint32_t boff = (uint32_t)kbB * 512u +
                                    (uint32_t)jb * 128u +
                                    ((uint32_t)(r8 ^ (kbB & 7)) << 4);
                    uint32_t w10, w11;
                    ldm_x2(w10, w11, sb + FS_W1 + boff);
                    mma_f16(accx, a2, w10, w11);
                }
            }
        }

        // ---- produce + publish seq0[s] -----------------------------------
        if (doL0) {
            float2 x0 = unpackh2(xa);
            float2 x1 = unpackh2(xb);
            float v0 = fmaxf(acc0[0] + x0.x, 0.f);
            float v1 = fmaxf(acc0[1] + x0.y, 0.f);
            float v2 = fmaxf(acc0[2] + x1.x, 0.f);
            float v3 = fmaxf(acc0[3] + x1.y, 0.f);
            uint32_t* hdst = s0ring + (size_t)(s & 1) * BB * HW;
            hdst[(size_t)brow * HW + (jcol >> 1)] = packh2(v0, v1);
            hdst[(size_t)(brow + 8) * HW + (jcol >> 1)] = packh2(v2, v3);
        }

        // ---- produce + publish h1[s-1] -----------------------------------
        if (haveA) {
            float v0 = fmaxf(accx[0] + bias1.x, 0.f);
            float v1 = fmaxf(accx[1] + bias1.y, 0.f);
            float v2 = fmaxf(accx[2] + bias1.x, 0.f);
            float v3 = fmaxf(accx[3] + bias1.y, 0.f);
            uint32_t* hdst = h1ring + (size_t)((s - 1) & 1) * BB * HW;
            hdst[(size_t)brow * HW + (jcol >> 1)] = packh2(v0, v1);
            hdst[(size_t)(brow + 8) * HW + (jcol >> 1)] = packh2(v2, v3);
            if (s - 1 == TT - 1) {
                *(float2*)(h_last + (size_t)brow * HH + jcol) =
                    make_float2(v0, v1);
                *(float2*)(h_last + (size_t)(brow + 8) * HH + jcol) =
                    make_float2(v2, v3);
            }
        }

        // fence-free barrier: target = (s+1) arrivals from each of 16 CTAs
        grp_bar(bt, (unsigned)(s + 1) * GRP);
    }
}

// ---------------- head: relu(h @ fc1^T + b1) @ fc2^T + b2 -------------------
__global__ __launch_bounds__(256) void head_kernel(
    const float* __restrict__ hl, const float* __restrict__ w1,
    const float* __restrict__ b1f, const float* __restrict__ w2,
    const float* __restrict__ b2f, float* __restrict__ out)
{
    __shared__ float sh[8];
    int b = blockIdx.x;
    int tid = threadIdx.x;
    int w = tid >> 5;
    int lane = tid & 31;

    const float* hb = hl + (size_t)b * HH;
    const float* wr = w1 + (size_t)w * HH;
    float ssum = 0.f;
    for (int k = lane; k < HH; k += 32) ssum += hb[k] * wr[k];
#pragma unroll
    for (int o = 16; o; o >>= 1) ssum += __shfl_xor_sync(0xffffffffu, ssum, o);
    if (lane == 0) sh[w] = fmaxf(ssum + b1f[w], 0.f);
    __syncthreads();
    if (tid < OO) {
        float r = b2f[tid];
#pragma unroll
        for (int j = 0; j < 8; ++j) r += sh[j] * w2[tid * 8 + j];
        out[(size_t)b * OO + tid] = r;
    }
}

// ---------------- launch ----------------------------------------------------
extern "C" void kernel_launch(void* const* d_in, const int* in_sizes, int n_in,
                              void* d_out, int out_size)
{
    const float* x     = (const float*)d_in[0];
    const float* w_ih0 = (const float*)d_in[1];
    const float* w_hh0 = (const float*)d_in[2];
    const float* b_ih0 = (const float*)d_in[3];
    const float* b_hh0 = (const float*)d_in[4];
    const float* w_ih1 = (const float*)d_in[5];
    const float* w_hh1 = (const float*)d_in[6];
    const float* b_ih1 = (const float*)d_in[7];
    const float* b_hh1 = (const float*)d_in[8];
    const float* fc1_w = (const float*)d_in[9];
    const float* fc1_b = (const float*)d_in[10];
    const float* fc2_w = (const float*)d_in[11];
    const float* fc2_b = (const float*)d_in[12];
    float* out = (float*)d_out;

    void* p;
    cudaGetSymbolAddress(&p, g_xp0);   uint32_t* xp0 = (uint32_t*)p;
    cudaGetSymbolAddress(&p, g_s0);    uint32_t* s0ring = (uint32_t*)p;
    cudaGetSymbolAddress(&p, g_h1);    uint32_t* h1ring = (uint32_t*)p;
    cudaGetSymbolAddress(&p, g_hlast); float* hlast = (float*)p;
    cudaGetSymbolAddress(&p, g_w0h);   __nv_bfloat16* w0h = (__nv_bfloat16*)p;
    cudaGetSymbolAddress(&p, g_w0l);   __nv_bfloat16* w0l = (__nv_bfloat16*)p;

    cudaFuncSetAttribute(fused_rec,
                         cudaFuncAttributeMaxDynamicSharedMemorySize,
                         FS_TOTAL);

    dim3 gg(TT * BB / 128, HH / 128);   // 512 x 4

    // layer-0 input projection weights -> bf16 hi/lo
    convert_w0<<<(HH * DD + 255) / 256, 256>>>(w_ih0);
    // layer-0 input projection: xp0 = x @ w_ih0^T + b_ih0 + b_hh0 (fp16 out)
    gemm_hmma<<<gg, 256>>>(x, w0h, w0l, b_ih0, b_hh0, xp0, DD, 1);
    // reset barrier counters, then fused dual-layer recurrence
    reset_bars<<<1, 32>>>();
    fused_rec<<<NBLK, 256, FS_TOTAL>>>(xp0, w_hh0, w_hh1, w_ih1,
                                       b_ih1, b_hh1, s0ring, h1ring, hlast);
    // head
    head_kernel<<<BB, 256>>>(hlast, fc1_w, fc1_b, fc2_w, fc2_b, out);
}